// round 4
// baseline (speedup 1.0000x reference)
#include <cuda_runtime.h>
#include <math.h>

// Problem constants (fixed by setup_inputs)
#define E_TOT   32768          // B*N*K = 1*1024*32
#define EDGE_D  32
#define MID_D   64
#define NC_IN   32
#define NC_OUT  32
#define M_IN    3
#define M_OUT   3
#define NFREQ   3
#define RDIM    96             // NC_IN * NFREQ
#define RAD_OUT 3072           // NC_OUT * RDIM

// Scratch: h2 transposed [k][e] for coalesced GEMM loads, tmp[e][r][m]
__device__ float g_h2T[MID_D * E_TOT];          // 8 MB
__device__ float g_tmp[E_TOT * RDIM * M_OUT];   // 37.75 MB (L2-resident)

__device__ __forceinline__ float warp_sum(float v) {
#pragma unroll
    for (int o = 16; o; o >>= 1) v += __shfl_xor_sync(0xffffffffu, v, o);
    return v;
}

__device__ __forceinline__ float gelu_exact(float x) {
    return 0.5f * x * (1.0f + erff(x * 0.70710678118654752f));
}

// ---------------------------------------------------------------------------
// Kernel 1: radial MLP (layers 1-2) + per-edge feats@basis.
// One warp per edge; 8 edges per 256-thread block.
// ---------------------------------------------------------------------------
__global__ __launch_bounds__(256) void k_mlp(
    const float* __restrict__ edges, const float* __restrict__ feats,
    const float* __restrict__ basis,
    const float* __restrict__ W1, const float* __restrict__ b1,
    const float* __restrict__ g1, const float* __restrict__ be1,
    const float* __restrict__ W2, const float* __restrict__ b2,
    const float* __restrict__ g2, const float* __restrict__ be2)
{
    __shared__ float W1s[EDGE_D * MID_D];   // 8 KB
    __shared__ float W2s[MID_D * MID_D];    // 16 KB
    __shared__ float b1s[64], g1s[64], be1s[64], b2s[64], g2s[64], be2s[64];

    int tid = threadIdx.x;
    for (int i = tid; i < EDGE_D * MID_D; i += 256) W1s[i] = W1[i];
    for (int i = tid; i < MID_D * MID_D; i += 256) W2s[i] = W2[i];
    if (tid < 64) {
        b1s[tid] = b1[tid]; g1s[tid] = g1[tid]; be1s[tid] = be1[tid];
        b2s[tid] = b2[tid]; g2s[tid] = g2[tid]; be2s[tid] = be2[tid];
    }
    __syncthreads();

    int warp = tid >> 5, lane = tid & 31;
    int e = blockIdx.x * 8 + warp;

    // ---- layer 1: x(32) @ W1(32x64) ----
    float x = edges[e * EDGE_D + lane];
    float a0 = b1s[lane], a1 = b1s[lane + 32];
#pragma unroll
    for (int i = 0; i < 32; i++) {
        float xi = __shfl_sync(0xffffffffu, x, i);
        a0 = fmaf(xi, W1s[i * 64 + lane], a0);
        a1 = fmaf(xi, W1s[i * 64 + 32 + lane], a1);
    }
    // LN (two-pass, matches jnp.var ddof=0)
    float mean = warp_sum(a0 + a1) * (1.0f / 64.0f);
    float d0 = a0 - mean, d1 = a1 - mean;
    float var = warp_sum(d0 * d0 + d1 * d1) * (1.0f / 64.0f);
    float inv = rsqrtf(var + 1e-5f);
    a0 = gelu_exact(d0 * inv * g1s[lane] + be1s[lane]);
    a1 = gelu_exact(d1 * inv * g1s[lane + 32] + be1s[lane + 32]);

    // ---- layer 2: h1(64) @ W2(64x64) ----
    float c0 = b2s[lane], c1 = b2s[lane + 32];
#pragma unroll
    for (int i = 0; i < 32; i++) {
        float xi = __shfl_sync(0xffffffffu, a0, i);
        c0 = fmaf(xi, W2s[i * 64 + lane], c0);
        c1 = fmaf(xi, W2s[i * 64 + 32 + lane], c1);
    }
#pragma unroll
    for (int i = 0; i < 32; i++) {
        float xi = __shfl_sync(0xffffffffu, a1, i);
        c0 = fmaf(xi, W2s[(i + 32) * 64 + lane], c0);
        c1 = fmaf(xi, W2s[(i + 32) * 64 + 32 + lane], c1);
    }
    mean = warp_sum(c0 + c1) * (1.0f / 64.0f);
    d0 = c0 - mean; d1 = c1 - mean;
    var = warp_sum(d0 * d0 + d1 * d1) * (1.0f / 64.0f);
    inv = rsqrtf(var + 1e-5f);
    c0 = gelu_exact(d0 * inv * g2s[lane] + be2s[lane]);
    c1 = gelu_exact(d1 * inv * g2s[lane + 32] + be2s[lane + 32]);

    // store transposed: g_h2T[k][e]
    g_h2T[lane * E_TOT + e] = c0;
    g_h2T[(lane + 32) * E_TOT + e] = c1;

    // ---- tmp[e][r=i*3+f][m] = sum_mi feats[e,i,mi] * basis[e,mi,f*3+m] ----
    // lane = i; column c = f*3+m, stored at e*288 + i*9 + c  (== r*3+m)
    float f0 = feats[e * 96 + lane * 3 + 0];
    float f1 = feats[e * 96 + lane * 3 + 1];
    float f2 = feats[e * 96 + lane * 3 + 2];
    const float* bs = basis + e * 27;
    float* tp = g_tmp + (size_t)e * 288 + lane * 9;
#pragma unroll
    for (int c = 0; c < 9; c++)
        tp[c] = fmaf(f0, bs[c], fmaf(f1, bs[9 + c], f2 * bs[18 + c]));
}

// ---------------------------------------------------------------------------
// Kernel 2: fused h2 @ W3 -> rw(64x96 per o) in registers -> contract w/ tmp.
// CTA: 64 edges, 256 threads = 16 (tx: r-groups of 6) x 16 (ty: e-groups of 4).
// Loops over all 32 output channels o; rw never hits memory.
// ---------------------------------------------------------------------------
__global__ __launch_bounds__(256) void k_main(
    const float* __restrict__ W3, float* __restrict__ out)
{
    __shared__ float Hs[MID_D * 64];   // Hs[k*64 + e] = h2[e0+e][k]   (16 KB)
    __shared__ float W3s[MID_D * 96];  // W3s[k*96 + r] = W3[k][o*96+r] (24 KB)

    int tid = threadIdx.x;
    int e0 = blockIdx.x * 64;
    int tx = tid & 15;   // r-group: r = tx*6 .. tx*6+5
    int ty = tid >> 4;   // e-group: e = ty*4 .. ty*4+3

    // Load H tile (coalesced from transposed h2, conflict-free STS)
    for (int i = tid; i < MID_D * 64; i += 256) {
        int k = i >> 6, e = i & 63;
        Hs[i] = g_h2T[k * E_TOT + e0 + e];
    }

    const float* tbase = g_tmp + (size_t)e0 * 288 + tx * 18;

    for (int o = 0; o < 32; ++o) {
        __syncthreads();  // previous GEMM reads of W3s done (and Hs ready, iter 0)
        // Load W3 o-slice: 64x96 floats as float4, coalesced
        for (int i = tid; i < (MID_D * 96) / 4; i += 256) {
            int k = i / 24, r4 = i % 24;
            ((float4*)W3s)[i] =
                *(const float4*)&W3[k * RAD_OUT + o * 96 + r4 * 4];
        }
        __syncthreads();

        float acc[4][6];
#pragma unroll
        for (int a = 0; a < 4; a++)
#pragma unroll
            for (int b = 0; b < 6; b++) acc[a][b] = 0.0f;

#pragma unroll 8
        for (int k = 0; k < MID_D; k++) {
            float4 h = *(const float4*)&Hs[k * 64 + ty * 4];
            const float* wr = &W3s[k * 96 + tx * 6];
            float w0 = wr[0], w1 = wr[1], w2 = wr[2];
            float w3 = wr[3], w4 = wr[4], w5 = wr[5];
            acc[0][0] = fmaf(h.x, w0, acc[0][0]); acc[0][1] = fmaf(h.x, w1, acc[0][1]);
            acc[0][2] = fmaf(h.x, w2, acc[0][2]); acc[0][3] = fmaf(h.x, w3, acc[0][3]);
            acc[0][4] = fmaf(h.x, w4, acc[0][4]); acc[0][5] = fmaf(h.x, w5, acc[0][5]);
            acc[1][0] = fmaf(h.y, w0, acc[1][0]); acc[1][1] = fmaf(h.y, w1, acc[1][1]);
            acc[1][2] = fmaf(h.y, w2, acc[1][2]); acc[1][3] = fmaf(h.y, w3, acc[1][3]);
            acc[1][4] = fmaf(h.y, w4, acc[1][4]); acc[1][5] = fmaf(h.y, w5, acc[1][5]);
            acc[2][0] = fmaf(h.z, w0, acc[2][0]); acc[2][1] = fmaf(h.z, w1, acc[2][1]);
            acc[2][2] = fmaf(h.z, w2, acc[2][2]); acc[2][3] = fmaf(h.z, w3, acc[2][3]);
            acc[2][4] = fmaf(h.z, w4, acc[2][4]); acc[2][5] = fmaf(h.z, w5, acc[2][5]);
            acc[3][0] = fmaf(h.w, w0, acc[3][0]); acc[3][1] = fmaf(h.w, w1, acc[3][1]);
            acc[3][2] = fmaf(h.w, w2, acc[3][2]); acc[3][3] = fmaf(h.w, w3, acc[3][3]);
            acc[3][4] = fmaf(h.w, w4, acc[3][4]); acc[3][5] = fmaf(h.w, w5, acc[3][5]);
        }

        // Epilogue: out[e, o, m] = sum_r rw[e, r] * tmp[e, r, m]
        // Each thread handles its 6 r's, then butterfly-reduce the 16 tx lanes.
#pragma unroll
        for (int e4 = 0; e4 < 4; e4++) {
            const float* tp = tbase + (ty * 4 + e4) * 288;
            float s0 = 0.f, s1 = 0.f, s2 = 0.f;
#pragma unroll
            for (int r = 0; r < 6; r++) {
                float c = acc[e4][r];
                s0 = fmaf(c, tp[r * 3 + 0], s0);
                s1 = fmaf(c, tp[r * 3 + 1], s1);
                s2 = fmaf(c, tp[r * 3 + 2], s2);
            }
#pragma unroll
            for (int m = 8; m; m >>= 1) {
                s0 += __shfl_xor_sync(0xffffffffu, s0, m);
                s1 += __shfl_xor_sync(0xffffffffu, s1, m);
                s2 += __shfl_xor_sync(0xffffffffu, s2, m);
            }
            if (tx == 0) {
                float* op = out + (size_t)(e0 + ty * 4 + e4) * 96 + o * 3;
                op[0] = s0; op[1] = s1; op[2] = s2;
            }
        }
    }
}

// ---------------------------------------------------------------------------
extern "C" void kernel_launch(void* const* d_in, const int* in_sizes, int n_in,
                              void* d_out, int out_size)
{
    const float* edges = (const float*)d_in[0];
    const float* feats = (const float*)d_in[1];
    const float* basis = (const float*)d_in[2];
    const float* W1    = (const float*)d_in[3];
    const float* b1    = (const float*)d_in[4];
    const float* g1    = (const float*)d_in[5];
    const float* be1   = (const float*)d_in[6];
    const float* W2    = (const float*)d_in[7];
    const float* b2    = (const float*)d_in[8];
    const float* g2    = (const float*)d_in[9];
    const float* be2   = (const float*)d_in[10];
    const float* W3    = (const float*)d_in[11];
    float* out = (float*)d_out;

    k_mlp<<<E_TOT / 8, 256>>>(edges, feats, basis, W1, b1, g1, be1,
                              W2, b2, g2, be2);
    k_main<<<E_TOT / 64, 256>>>(W3, out);
}

// round 5
// speedup vs baseline: 1.1463x; 1.1463x over previous
#include <cuda_runtime.h>
#include <math.h>

// Problem constants (fixed by setup_inputs)
#define E_TOT   32768          // B*N*K = 1*1024*32
#define EDGE_D  32
#define MID_D   64
#define NC_IN   32
#define NC_OUT  32
#define M_IN    3
#define M_OUT   3
#define NFREQ   3
#define RDIM    96             // NC_IN * NFREQ
#define RAD_OUT 3072           // NC_OUT * RDIM

typedef unsigned long long u64;

// Scratch: h2 transposed [k][e] for coalesced GEMM loads, tmp[e][r][m]
__device__ float g_h2T[MID_D * E_TOT];          // 8 MB
__device__ float g_tmp[E_TOT * RDIM * M_OUT];   // 37.75 MB

__device__ __forceinline__ float warp_sum(float v) {
#pragma unroll
    for (int o = 16; o; o >>= 1) v += __shfl_xor_sync(0xffffffffu, v, o);
    return v;
}

__device__ __forceinline__ float gelu_exact(float x) {
    return 0.5f * x * (1.0f + erff(x * 0.70710678118654752f));
}

// packed fp32x2 FMA: d = a * b + d (per 32-bit half, exact fp32)
__device__ __forceinline__ void ffma2(u64& d, u64 a, u64 b) {
    asm("fma.rn.f32x2 %0, %1, %2, %0;" : "+l"(d) : "l"(a), "l"(b));
}
__device__ __forceinline__ u64 dup2(float w) {
    u64 r;
    asm("mov.b64 %0, {%1, %1};" : "=l"(r) : "f"(w));
    return r;
}
__device__ __forceinline__ float lo32(u64 v) {
    return __int_as_float((int)(unsigned)(v & 0xffffffffu));
}
__device__ __forceinline__ float hi32(u64 v) {
    return __int_as_float((int)(unsigned)(v >> 32));
}

// ---------------------------------------------------------------------------
// Kernel 1: radial MLP (layers 1-2) + per-edge feats@basis. (unchanged)
// One warp per edge; 8 edges per 256-thread block.
// ---------------------------------------------------------------------------
__global__ __launch_bounds__(256) void k_mlp(
    const float* __restrict__ edges, const float* __restrict__ feats,
    const float* __restrict__ basis,
    const float* __restrict__ W1, const float* __restrict__ b1,
    const float* __restrict__ g1, const float* __restrict__ be1,
    const float* __restrict__ W2, const float* __restrict__ b2,
    const float* __restrict__ g2, const float* __restrict__ be2)
{
    __shared__ float W1s[EDGE_D * MID_D];
    __shared__ float W2s[MID_D * MID_D];
    __shared__ float b1s[64], g1s[64], be1s[64], b2s[64], g2s[64], be2s[64];

    int tid = threadIdx.x;
    for (int i = tid; i < EDGE_D * MID_D; i += 256) W1s[i] = W1[i];
    for (int i = tid; i < MID_D * MID_D; i += 256) W2s[i] = W2[i];
    if (tid < 64) {
        b1s[tid] = b1[tid]; g1s[tid] = g1[tid]; be1s[tid] = be1[tid];
        b2s[tid] = b2[tid]; g2s[tid] = g2[tid]; be2s[tid] = be2[tid];
    }
    __syncthreads();

    int warp = tid >> 5, lane = tid & 31;
    int e = blockIdx.x * 8 + warp;

    float x = edges[e * EDGE_D + lane];
    float a0 = b1s[lane], a1 = b1s[lane + 32];
#pragma unroll
    for (int i = 0; i < 32; i++) {
        float xi = __shfl_sync(0xffffffffu, x, i);
        a0 = fmaf(xi, W1s[i * 64 + lane], a0);
        a1 = fmaf(xi, W1s[i * 64 + 32 + lane], a1);
    }
    float mean = warp_sum(a0 + a1) * (1.0f / 64.0f);
    float d0 = a0 - mean, d1 = a1 - mean;
    float var = warp_sum(d0 * d0 + d1 * d1) * (1.0f / 64.0f);
    float inv = rsqrtf(var + 1e-5f);
    a0 = gelu_exact(d0 * inv * g1s[lane] + be1s[lane]);
    a1 = gelu_exact(d1 * inv * g1s[lane + 32] + be1s[lane + 32]);

    float c0 = b2s[lane], c1 = b2s[lane + 32];
#pragma unroll
    for (int i = 0; i < 32; i++) {
        float xi = __shfl_sync(0xffffffffu, a0, i);
        c0 = fmaf(xi, W2s[i * 64 + lane], c0);
        c1 = fmaf(xi, W2s[i * 64 + 32 + lane], c1);
    }
#pragma unroll
    for (int i = 0; i < 32; i++) {
        float xi = __shfl_sync(0xffffffffu, a1, i);
        c0 = fmaf(xi, W2s[(i + 32) * 64 + lane], c0);
        c1 = fmaf(xi, W2s[(i + 32) * 64 + 32 + lane], c1);
    }
    mean = warp_sum(c0 + c1) * (1.0f / 64.0f);
    d0 = c0 - mean; d1 = c1 - mean;
    var = warp_sum(d0 * d0 + d1 * d1) * (1.0f / 64.0f);
    inv = rsqrtf(var + 1e-5f);
    c0 = gelu_exact(d0 * inv * g2s[lane] + be2s[lane]);
    c1 = gelu_exact(d1 * inv * g2s[lane + 32] + be2s[lane + 32]);

    g_h2T[lane * E_TOT + e] = c0;
    g_h2T[(lane + 32) * E_TOT + e] = c1;

    float f0 = feats[e * 96 + lane * 3 + 0];
    float f1 = feats[e * 96 + lane * 3 + 1];
    float f2 = feats[e * 96 + lane * 3 + 2];
    const float* bs = basis + e * 27;
    float* tp = g_tmp + (size_t)e * 288 + lane * 9;
#pragma unroll
    for (int c = 0; c < 9; c++)
        tp[c] = fmaf(f0, bs[c], fmaf(f1, bs[9 + c], f2 * bs[18 + c]));
}

// ---------------------------------------------------------------------------
// Kernel 2: fused h2 @ W3 -> rw in registers (f32x2 packed) -> contract w/ tmp.
// CTA: 128 edges, 128 threads = 8 (tx: r-groups of 12) x 16 (ty: 8 edges).
// Thread tile: 8 edges (4 packed pairs) x 12 r = 48 FFMA2 per k-step.
// K loop split in two 32-k passes so W3 slice fits static SMEM (44 KB total).
// ---------------------------------------------------------------------------
__global__ __launch_bounds__(128) void k_main(
    const float* __restrict__ W3, float* __restrict__ out)
{
    __shared__ float Hs[MID_D * 128];   // Hs[k*128 + e]           32 KB
    __shared__ float W3s[32 * 96];      // W3s[kk*96 + r] (half-K) 12 KB

    int tid = threadIdx.x;
    int e0 = blockIdx.x * 128;
    int tx = tid & 7;    // r-group: r = tx*12 .. tx*12+11
    int ty = tid >> 3;   // edges ty*8 .. ty*8+7

    // Load H tile (coalesced from transposed h2)
    {
        float4* Hs4 = (float4*)Hs;
        for (int i = tid; i < (MID_D * 128) / 4; i += 128) {
            int k = i >> 5, e4 = i & 31;
            Hs4[i] = *(const float4*)&g_h2T[k * E_TOT + e0 + e4 * 4];
        }
    }

    const float* tbase = g_tmp + (size_t)e0 * 288 + tx * 36;

    for (int o = 0; o < 32; ++o) {
        u64 acc[4][12];
#pragma unroll
        for (int p = 0; p < 4; p++)
#pragma unroll
            for (int r = 0; r < 12; r++) acc[p][r] = 0ull;

        for (int pass = 0; pass < 2; ++pass) {
            __syncthreads();   // protect W3s from previous readers (covers Hs @o=0)
            // Load half-K W3 slice: rows pass*32..+31, cols o*96..+95
            for (int i = tid; i < (32 * 96) / 4; i += 128) {
                int kk = i / 24, r4 = i % 24;
                ((float4*)W3s)[i] = *(const float4*)
                    &W3[(pass * 32 + kk) * RAD_OUT + o * 96 + r4 * 4];
            }
            __syncthreads();

#pragma unroll 8
            for (int kk = 0; kk < 32; kk++) {
                const ulonglong2* hrow = (const ulonglong2*)
                    &Hs[(pass * 32 + kk) * 128 + ty * 8];
                ulonglong2 hA = hrow[0], hB = hrow[1];
                const float2* wr = (const float2*)&W3s[kk * 96 + tx * 12];
                float2 w01 = wr[0], w23 = wr[1], w45 = wr[2];
                float2 w67 = wr[3], w89 = wr[4], wAB = wr[5];
                u64 wd[12];
                wd[0]  = dup2(w01.x); wd[1]  = dup2(w01.y);
                wd[2]  = dup2(w23.x); wd[3]  = dup2(w23.y);
                wd[4]  = dup2(w45.x); wd[5]  = dup2(w45.y);
                wd[6]  = dup2(w67.x); wd[7]  = dup2(w67.y);
                wd[8]  = dup2(w89.x); wd[9]  = dup2(w89.y);
                wd[10] = dup2(wAB.x); wd[11] = dup2(wAB.y);
#pragma unroll
                for (int r = 0; r < 12; r++) {
                    ffma2(acc[0][r], hA.x, wd[r]);
                    ffma2(acc[1][r], hA.y, wd[r]);
                    ffma2(acc[2][r], hB.x, wd[r]);
                    ffma2(acc[3][r], hB.y, wd[r]);
                }
            }
        }

        // Epilogue: out[e, o, m] = sum_r rw[e, r] * tmp[e, r, m]
        // Each thread contracts its 12 r's; butterfly over the 8 tx lanes.
#pragma unroll
        for (int p = 0; p < 4; p++) {
#pragma unroll
            for (int hh = 0; hh < 2; hh++) {
                int e = ty * 8 + p * 2 + hh;
                const float4* tp = (const float4*)(tbase + (size_t)e * 288);
                float s0 = 0.f, s1 = 0.f, s2 = 0.f;
#pragma unroll
                for (int c = 0; c < 3; c++) {     // 3 chunks of 4 r's
                    float4 t0 = tp[c * 3 + 0];
                    float4 t1 = tp[c * 3 + 1];
                    float4 t2 = tp[c * 3 + 2];
                    float tv[12] = {t0.x, t0.y, t0.z, t0.w,
                                    t1.x, t1.y, t1.z, t1.w,
                                    t2.x, t2.y, t2.z, t2.w};
#pragma unroll
                    for (int rr = 0; rr < 4; rr++) {
                        u64 a = acc[p][c * 4 + rr];
                        float cv = hh ? hi32(a) : lo32(a);
                        s0 = fmaf(cv, tv[rr * 3 + 0], s0);
                        s1 = fmaf(cv, tv[rr * 3 + 1], s1);
                        s2 = fmaf(cv, tv[rr * 3 + 2], s2);
                    }
                }
#pragma unroll
                for (int m = 4; m; m >>= 1) {
                    s0 += __shfl_xor_sync(0xffffffffu, s0, m);
                    s1 += __shfl_xor_sync(0xffffffffu, s1, m);
                    s2 += __shfl_xor_sync(0xffffffffu, s2, m);
                }
                if (tx == 0) {
                    float* op = out + (size_t)(e0 + e) * 96 + o * 3;
                    op[0] = s0; op[1] = s1; op[2] = s2;
                }
            }
        }
    }
}

// ---------------------------------------------------------------------------
extern "C" void kernel_launch(void* const* d_in, const int* in_sizes, int n_in,
                              void* d_out, int out_size)
{
    const float* edges = (const float*)d_in[0];
    const float* feats = (const float*)d_in[1];
    const float* basis = (const float*)d_in[2];
    const float* W1    = (const float*)d_in[3];
    const float* b1    = (const float*)d_in[4];
    const float* g1    = (const float*)d_in[5];
    const float* be1   = (const float*)d_in[6];
    const float* W2    = (const float*)d_in[7];
    const float* b2    = (const float*)d_in[8];
    const float* g2    = (const float*)d_in[9];
    const float* be2   = (const float*)d_in[10];
    const float* W3    = (const float*)d_in[11];
    float* out = (float*)d_out;

    k_mlp<<<E_TOT / 8, 256>>>(edges, feats, basis, W1, b1, g1, be1,
                              W2, b2, g2, be2);
    k_main<<<E_TOT / 128, 128>>>(W3, out);
}